// round 13
// baseline (speedup 1.0000x reference)
#include <cuda_runtime.h>

// SWT db4, 3 levels, wrap. x:(64,32,4096) f32 -> out:(64,32,4096,4) = [a3,d3,d2,d1].
// out[t] = sum_j f[j] * in[(t + (4-j)*dil) mod 4096], dil = 1,2,4.
//
// R13 = R11 (phase-deinterleaved level 3, conflict-free strides) minus overhead:
//   - QMF: fhi[j] == (-1)^(j+1) * flo[7-j] exactly -> no fhi regs, signs folded
//     into FFMA neg modifiers.
//   - phase halo writes moved out of the hot loop into a tiny 28-thread copy
//     step between barriers (replaces 16 predicated STS per thread).

#define SWT_T   4096
#define SWT_G   1024
#define SWT_NT  512

#define X_CORE    1                   // x granule core offset (granules)
#define B_CORE    2                   // lo1 granule core offset
#define PH_STRIDE 1048                // floats per lo2-phase array  (24 mod 32)
#define D_STRIDE  1032                // floats per d1/d2 phase array ( 8 mod 32)

#define OFF_B    4192                 // floats: after phase region (4*1048)
#define OFF_D2   (OFF_B + 1029 * 4)   // 8308
#define OFF_D1   (OFF_D2 + 4 * D_STRIDE)      // 12436
#define SMEM_FLOATS (OFF_D1 + 4 * D_STRIDE)   // 16564
#define SMEM_BYTES  (SMEM_FLOATS * 4)         // 66256

// hi-filter FMA via QMF: fhi[j] = (-1)^(j+1) * flo[7-j]  (bitwise exact for db4)
#define HI_FMA(acc, j, v) \
    (acc) = ((j) & 1) ? fmaf(flo[7 - (j)], (v), (acc)) \
                      : fmaf(-flo[7 - (j)], (v), (acc))

__global__ __launch_bounds__(SWT_NT, 3)
void swt_db4_l3_kernel(const float* __restrict__ x,
                       const float* __restrict__ dec_lo,
                       const float* __restrict__ dec_hi,
                       float4* __restrict__ out)
{
    extern __shared__ float smem_f[];
    float4* s_a   = reinterpret_cast<float4*>(smem_f);            // x (overlaid by phases)
    float4* s_b   = reinterpret_cast<float4*>(smem_f + OFF_B);    // lo1
    float*  s_ph  = smem_f;                                       // 4 lo2-phase arrays
    float*  s_d2p = smem_f + OFF_D2;                              // 4 d2-phase arrays
    float*  s_d1p = smem_f + OFF_D1;                              // 4 d1-phase arrays

    const int row = blockIdx.x;
    const int tid = threadIdx.x;

    float flo[8];
#pragma unroll
    for (int j = 0; j < 8; ++j)
        flo[j] = __ldg(&dec_lo[j]);

    // ---- Load x row + wrap halos (granules [-1, 1026) around core) ----
    const float4* xr4 = reinterpret_cast<const float4*>(x + (size_t)row * SWT_T);
#pragma unroll
    for (int s = 0; s < 2; ++s) {
        const int g = tid + s * SWT_NT;
        float4 v = xr4[g];
        s_a[X_CORE + g] = v;
        if (g == SWT_G - 1) s_a[0] = v;                      // left halo: x[4092..)
        if (g < 2)          s_a[X_CORE + SWT_G + g] = v;     // right halo: x[0..8)
    }
    __syncthreads();

    // ---- Pass 1 (dil=1): lo1 -> s_b (+halos), d1 -> phase staging.
    //      Window [t0-4, t0+8) = x granules g-1..g+1. ----
#pragma unroll
    for (int s = 0; s < 2; ++s) {
        const int g = tid + s * SWT_NT;          // t0 = 4g
        float lo1[4] = {0.f, 0.f, 0.f, 0.f};
        float hi1[4] = {0.f, 0.f, 0.f, 0.f};
#pragma unroll
        for (int i = 0; i < 3; ++i) {
            const float4 w = s_a[g + i];         // x granule g-1+i
            const float wv[4] = {w.x, w.y, w.z, w.w};
#pragma unroll
            for (int p = 0; p < 4; ++p) {
                const int o = 4 * i - 4 + p;
#pragma unroll
                for (int c = 0; c < 4; ++c) {
                    const int j = 4 - o + c;     // o = c + (4-j)
                    if (j >= 0 && j <= 7) {
                        lo1[c] = fmaf(flo[j], wv[p], lo1[c]);
                        HI_FMA(hi1[c], j, wv[p]);
                    }
                }
            }
        }
        const float4 v = make_float4(lo1[0], lo1[1], lo1[2], lo1[3]);
        s_b[B_CORE + g] = v;
        if (g >= SWT_G - 2) s_b[B_CORE + g - SWT_G] = v;      // left halo (2)
        if (g < 2)          s_b[B_CORE + SWT_G + g] = v;      // right halo (2)
#pragma unroll
        for (int c = 0; c < 4; ++c)
            s_d1p[c * D_STRIDE + g] = hi1[c];                 // phase-deinterleaved
    }
    __syncthreads();   // all p1 reads of s_a(x) retired; phases may overlay A

    // ---- Pass 2 (dil=2): lo2 phases -> s_ph (no halos here), d2 -> staging.
    //      Window [t0-8, t0+12) = lo1 granules g-2..g+2. ----
#pragma unroll
    for (int s = 0; s < 2; ++s) {
        const int g = tid + s * SWT_NT;
        float lo2[4] = {0.f, 0.f, 0.f, 0.f};
        float hi2[4] = {0.f, 0.f, 0.f, 0.f};
#pragma unroll
        for (int i = 0; i < 5; ++i) {
            const float4 w = s_b[g + i];         // lo1 granule g-2+i
            const float wv[4] = {w.x, w.y, w.z, w.w};
#pragma unroll
            for (int p = 0; p < 4; ++p) {
                const int o = 4 * i - 8 + p;
#pragma unroll
                for (int c = (o & 1); c < 4; c += 2) {
                    const int j = 4 - (o - c) / 2;   // o = c + 2(4-j)
                    if (j >= 0 && j <= 7) {
                        lo2[c] = fmaf(flo[j], wv[p], lo2[c]);
                        HI_FMA(hi2[c], j, wv[p]);
                    }
                }
            }
        }
        // lo2[c] at t = 4g+c -> phase c, position g (core only; halos copied below)
#pragma unroll
        for (int c = 0; c < 4; ++c) {
            s_ph[c * PH_STRIDE + 4 + g] = lo2[c];
            s_d2p[c * D_STRIDE + g]     = hi2[c];
        }
    }
    __syncthreads();

    // ---- Phase halo copy: left 3 (q=1021..1023 -> [-3,-1]), right 4 ([1024..1027]=q 0..3) ----
    if (tid < 28) {
        const int c = tid / 7, k = tid % 7;
        float* ph = s_ph + c * PH_STRIDE + 4;
        if (k < 3) ph[k - 3]        = ph[1021 + k];
        else       ph[1024 + k - 3] = ph[k - 3];
    }
    __syncthreads();

    // ---- Pass 3 (dil=1 in phase space): a3/d3 from phases, merge d2/d1.
    //      out3[4q+c] = sum_j f[j] * phase[c][q+4-j].
    //      Thread: phase c = tid&3, 4 consecutive q from q0 = (tid>>2)*4 + r*512. ----
    float4* out_row = out + (size_t)row * SWT_T;
    const int c  = tid & 3;
    const int qb = tid >> 2;
    const float* ph  = s_ph + c * PH_STRIDE + 4;
    const float* d1p = s_d1p + c * D_STRIDE;
    const float* d2p = s_d2p + c * D_STRIDE;
#pragma unroll
    for (int r = 0; r < 2; ++r) {
        const int q0 = qb * 4 + r * (SWT_T / 8);   // 0..1020 step 4
        const float4 w0 = *reinterpret_cast<const float4*>(ph + q0 - 4);
        const float4 w1 = *reinterpret_cast<const float4*>(ph + q0);
        const float4 w2 = *reinterpret_cast<const float4*>(ph + q0 + 4);
        const float win[12] = {w0.x, w0.y, w0.z, w0.w,
                               w1.x, w1.y, w1.z, w1.w,
                               w2.x, w2.y, w2.z, w2.w};
        const float4 d1v = *reinterpret_cast<const float4*>(d1p + q0);
        const float4 d2v = *reinterpret_cast<const float4*>(d2p + q0);
        const float d1a[4] = {d1v.x, d1v.y, d1v.z, d1v.w};
        const float d2a[4] = {d2v.x, d2v.y, d2v.z, d2v.w};
#pragma unroll
        for (int u = 0; u < 4; ++u) {
            float a3 = 0.f, d3 = 0.f;
#pragma unroll
            for (int j = 0; j < 8; ++j) {
                const float v = win[u + 8 - j];    // phase[c][q0+u+4-j]
                a3 = fmaf(flo[j], v, a3);
                HI_FMA(d3, j, v);
            }
            out_row[4 * (q0 + u) + c] = make_float4(a3, d3, d2a[u], d1a[u]);
        }
    }
}

extern "C" void kernel_launch(void* const* d_in, const int* in_sizes, int n_in,
                              void* d_out, int out_size)
{
    const float* x      = (const float*)d_in[0];
    const float* dec_lo = (const float*)d_in[1];
    const float* dec_hi = (const float*)d_in[2];
    float4* out         = (float4*)d_out;
    (void)dec_hi;   // reconstructed via QMF identity from dec_lo

    cudaFuncSetAttribute(swt_db4_l3_kernel,
                         cudaFuncAttributeMaxDynamicSharedMemorySize, SMEM_BYTES);

    const int rows = in_sizes[0] / SWT_T;   // 2048
    swt_db4_l3_kernel<<<rows, SWT_NT, SMEM_BYTES>>>(x, dec_lo, dec_hi, out);
}

// round 16
// speedup vs baseline: 1.0562x; 1.0562x over previous
#include <cuda_runtime.h>

// SWT db4, 3 levels, wrap. x:(64,32,4096) f32 -> out:(64,32,4096,4) = [a3,d3,d2,d1].
// out[t] = sum_j f[j] * in[(t + (4-j)*dil) mod 4096], dil = 1,2,4.
//
// R15 = half-row CTAs (2 CTAs/row, 256 threads, 33.2 KB SMEM -> 6 CTAs/SM so
// barrier-separated phases of different CTAs overlap on the L1 crossbar), with
// the pass-3 base-pointer fix: the lo2 overlay buffer holds lo2[f-12] at float
// index f, so lo2[t+4i-12] is read at index t+4i FROM THE BASE.
// QMF: fhi[j] = (-1)^(j+1) * flo[7-j] (bitwise exact for db4).

#define SWT_T   4096
#define ROW_G   1024            // float4 granules per full row
#define H       2048            // elems per half-row (CTA)
#define HG      512             // granules per half-row
#define NT      256

#define X_CORE   6              // granule of h0 in x buffer   (left 24 floats)
#define LO1_CORE 5              //                             (left 20 floats)
#define LO2_CORE 3              //                             (left 12 floats)
#define X_GRAN   526            // granules [-6, 520)
#define LO1_GRAN 523            // granules [-5, 518)
#define LO2_GRAN 519            // granules [-3, 516)  (overlays x buffer)

#define OFF_LO1  (X_GRAN * 4)               // 2104 floats
#define OFF_D1   (OFF_LO1 + LO1_GRAN * 4)   // 4196
#define OFF_D2   (OFF_D1 + H)               // 6244
#define SMEM_FLOATS (OFF_D2 + H)            // 8292
#define SMEM_BYTES  (SMEM_FLOATS * 4)       // 33168

// hi-filter FMA via QMF: fhi[j] = (-1)^(j+1) * flo[7-j]
#define HI_FMA(acc, j, v) \
    (acc) = ((j) & 1) ? fmaf(flo[7 - (j)], (v), (acc)) \
                      : fmaf(-flo[7 - (j)], (v), (acc))

__global__ __launch_bounds__(NT, 6)
void swt_db4_l3_kernel(const float* __restrict__ x,
                       const float* __restrict__ dec_lo,
                       const float* __restrict__ dec_hi,
                       float4* __restrict__ out)
{
    extern __shared__ float smem_f[];
    float4* s_x   = reinterpret_cast<float4*>(smem_f);            // x, later lo2
    float4* s_lo1 = reinterpret_cast<float4*>(smem_f + OFF_LO1);
    float*  s_d1  = smem_f + OFF_D1;                              // [2048]
    float*  s_d2  = smem_f + OFF_D2;                              // [2048]

    const int row  = blockIdx.x >> 1;
    const int half = blockIdx.x & 1;
    const int g0   = half * HG;          // first core granule (in-row)
    const int tid  = threadIdx.x;

    float flo[8];
#pragma unroll
    for (int j = 0; j < 8; ++j)
        flo[j] = __ldg(&dec_lo[j]);

    // ---- Load x half-row + cascaded halos (granules g0-6 .. g0+519, wrap) ----
    const float4* xrow = reinterpret_cast<const float4*>(x + (size_t)row * SWT_T);
#pragma unroll
    for (int k = tid; k < X_GRAN; k += NT)
        s_x[k] = xrow[(g0 - X_CORE + k) & (ROW_G - 1)];
    __syncthreads();

    // ---- Pass 1 (dil=1): lo1 granules [-5,518), d1 core only.
    //      lo1 granule gc needs x granules gc-1..gc+1 = s_x[idx + i]. ----
    for (int idx = tid; idx < LO1_GRAN; idx += NT) {
        const int gc = idx - LO1_CORE;             // -5 .. 517
        float lo1[4] = {0.f, 0.f, 0.f, 0.f};
        float hi1[4] = {0.f, 0.f, 0.f, 0.f};
#pragma unroll
        for (int i = 0; i < 3; ++i) {
            const float4 w = s_x[idx + i];         // x granule gc-1+i
            const float wv[4] = {w.x, w.y, w.z, w.w};
#pragma unroll
            for (int p = 0; p < 4; ++p) {
                const int o = 4 * i - 4 + p;       // offset from t0=4gc
#pragma unroll
                for (int c = 0; c < 4; ++c) {
                    const int j = 4 - o + c;       // o = c + (4-j)
                    if (j >= 0 && j <= 7) {
                        lo1[c] = fmaf(flo[j], wv[p], lo1[c]);
                        HI_FMA(hi1[c], j, wv[p]);
                    }
                }
            }
        }
        s_lo1[idx] = make_float4(lo1[0], lo1[1], lo1[2], lo1[3]);
        if ((unsigned)gc < HG)
            reinterpret_cast<float4*>(s_d1)[gc] =
                make_float4(hi1[0], hi1[1], hi1[2], hi1[3]);
    }
    __syncthreads();   // lo1 complete; x dead -> lo2 may overlay s_x

    // ---- Pass 2 (dil=2): lo2 granules [-3,516) -> s_x overlay, d2 core only.
    //      lo2 granule gc needs lo1 granules gc-2..gc+2 = s_lo1[idx + i]. ----
    for (int idx = tid; idx < LO2_GRAN; idx += NT) {
        const int gc = idx - LO2_CORE;             // -3 .. 515
        float lo2[4] = {0.f, 0.f, 0.f, 0.f};
        float hi2[4] = {0.f, 0.f, 0.f, 0.f};
#pragma unroll
        for (int i = 0; i < 5; ++i) {
            const float4 w = s_lo1[idx + i];       // lo1 granule gc-2+i
            const float wv[4] = {w.x, w.y, w.z, w.w};
#pragma unroll
            for (int p = 0; p < 4; ++p) {
                const int o = 4 * i - 8 + p;
#pragma unroll
                for (int c = (o & 1); c < 4; c += 2) {
                    const int j = 4 - (o - c) / 2; // o = c + 2(4-j)
                    if (j >= 0 && j <= 7) {
                        lo2[c] = fmaf(flo[j], wv[p], lo2[c]);
                        HI_FMA(hi2[c], j, wv[p]);
                    }
                }
            }
        }
        s_x[idx] = make_float4(lo2[0], lo2[1], lo2[2], lo2[3]);
        if ((unsigned)gc < HG)
            reinterpret_cast<float4*>(s_d2)[gc] =
                make_float4(hi2[0], hi2[1], hi2[2], hi2[3]);
    }
    __syncthreads();

    // ---- Pass 3 (dil=4), scalar: a3/d3 from lo2, merge d1/d2, STG.128.
    //      smem_f[f] = lo2[f - 12]  ->  lo2[t + 4i - 12] = smem_f[t + 4i]. ----
    const float* lo2f = smem_f;                    // base (holds lo2 shifted by -12)
    float4* outp = out + (size_t)row * SWT_T + half * H;
#pragma unroll
    for (int r = 0; r < H / NT; ++r) {             // 8
        const int t = tid + r * NT;
        float a3 = 0.f, d3 = 0.f;
#pragma unroll
        for (int i = 0; i < 8; ++i) {
            const float v = lo2f[t + 4 * i];       // lo2[t + 4i - 12], j = 7-i
            a3 = fmaf(flo[7 - i], v, a3);
            HI_FMA(d3, 7 - i, v);
        }
        outp[t] = make_float4(a3, d3, s_d2[t], s_d1[t]);
    }
}

extern "C" void kernel_launch(void* const* d_in, const int* in_sizes, int n_in,
                              void* d_out, int out_size)
{
    const float* x      = (const float*)d_in[0];
    const float* dec_lo = (const float*)d_in[1];
    const float* dec_hi = (const float*)d_in[2];
    float4* out         = (float4*)d_out;
    (void)dec_hi;   // reconstructed via QMF identity from dec_lo

    cudaFuncSetAttribute(swt_db4_l3_kernel,
                         cudaFuncAttributeMaxDynamicSharedMemorySize, SMEM_BYTES);

    const int rows = in_sizes[0] / SWT_T;   // 2048
    swt_db4_l3_kernel<<<rows * 2, NT, SMEM_BYTES>>>(x, dec_lo, dec_hi, out);
}